// round 7
// baseline (speedup 1.0000x reference)
#include <cuda_runtime.h>
#include <mma.h>
#include <math.h>

using namespace nvcuda;

#define TSZ   512
#define INSZ  1024
#define HIDSZ 1024
#define BH    65536                        // 64*1024
static constexpr size_t TBH = 33554432ull; // 512*64*1024

#define NCTA  64
#define NTHR  256

// Device-global scratch (no allocations allowed)
__device__ float g_gates[3ull * TBH];           // stage1 out [gate][t*64+b][hid]
__device__ float g_Wall[6ull * 1048576];        // tf32 W: [hr|hz|hn|ir|iz|in]
__device__ float g_xt[32768ull * 1024];         // tf32 x, time-major [t*64+b][k]
__device__ float g_ht[2][BH];                   // tf32 h ping-pong
__device__ unsigned g_flags[NCTA];              // monotonic h-publication flags

// ---------------------------------------------------------------------------
__device__ __forceinline__ void cp16(void* sdst, const void* gsrc) {
    unsigned s = (unsigned)__cvta_generic_to_shared(sdst);
    asm volatile("cp.async.cg.shared.global [%0], [%1], 16;" :: "r"(s), "l"(gsrc));
}
#define CP_COMMIT() asm volatile("cp.async.commit_group;")
#define CP_WAIT0()  asm volatile("cp.async.wait_group 0;")

__device__ __forceinline__ unsigned ld_acq(const unsigned* p) {
    unsigned v;
    asm volatile("ld.acquire.gpu.u32 %0, [%1];" : "=r"(v) : "l"(p) : "memory");
    return v;
}
__device__ __forceinline__ void st_rel(unsigned* p, unsigned v) {
    asm volatile("st.release.gpu.u32 [%0], %1;" :: "l"(p), "r"(v) : "memory");
}

// Wait until the 8 producers of h-chunk c (32 cols per kgrp) reach `target`.
// Producer of cols [16p, 16p+16): chunk c, kgrp kg -> p = 16*kg + 2c (+1).
__device__ __forceinline__ void poll_chunk(int c, unsigned target, int tid) {
    if (tid < 8) {
        int p = ((tid >> 1) << 4) + (c << 1) + (tid & 1);
        while ((int)(ld_acq(&g_flags[p]) - target) < 0) { }
    }
}

// ---------------------------------------------------------------------------
// Prep: tf32-round weights; tf32-round + time-major-transpose x.
// ---------------------------------------------------------------------------
__global__ void wconv_kernel(const float* __restrict__ src, int which) {
    int i = blockIdx.x * 256 + threadIdx.x;
    float4 v = ((const float4*)src)[i];
    v.x = wmma::__float_to_tf32(v.x); v.y = wmma::__float_to_tf32(v.y);
    v.z = wmma::__float_to_tf32(v.z); v.w = wmma::__float_to_tf32(v.w);
    ((float4*)(g_Wall + (size_t)which * 1048576))[i] = v;
}

__global__ void xprep_kernel(const float* __restrict__ x) {
    int m = blockIdx.x;
    int t = m >> 6, b = m & 63;
    int c = threadIdx.x;
    float4 v = ((const float4*)(x + ((size_t)b * TSZ + t) * INSZ))[c];
    v.x = wmma::__float_to_tf32(v.x); v.y = wmma::__float_to_tf32(v.y);
    v.z = wmma::__float_to_tf32(v.z); v.w = wmma::__float_to_tf32(v.w);
    ((float4*)(g_xt + (size_t)m * 1024))[c] = v;
}

// ---------------------------------------------------------------------------
// Stage 1: gates[g][m][n] = xt[m,:] @ W_g[:,n]. 128m x 64n tiles, K-chunk 32,
// cp.async double-buffered. Dyn smem 54272 B.
// ---------------------------------------------------------------------------
#define S1_SMEM 54272

__global__ __launch_bounds__(256)
void stage1_kernel() {
    extern __shared__ __align__(16) float s1[];
    const int gate = blockIdx.x >> 4;
    const int col0 = (blockIdx.x & 15) << 6;
    const int m0   = blockIdx.y << 7;
    const float* Wp = g_Wall + (size_t)(3 + gate) * 1048576;

    const int tid  = threadIdx.x;
    const int wid  = tid >> 5;
    const int mrow = wid & 3;
    const int ncol = wid >> 2;

    wmma::fragment<wmma::accumulator, 16, 16, 8, float> acc[2][2];
#pragma unroll
    for (int i = 0; i < 2; i++)
#pragma unroll
        for (int j = 0; j < 2; j++) wmma::fill_fragment(acc[i][j], 0.0f);

#define S1_ISSUE(c)                                                             \
    {                                                                           \
        float* As = s1 + ((c) & 1) * 6784;                                      \
        float* Bs = As + 4608;                                                  \
        _Pragma("unroll")                                                       \
        for (int q = 0; q < 4; q++) {                                           \
            int o = tid + q * 256;                                              \
            int row = o >> 3, c4 = (o & 7) << 2;                                \
            cp16(As + row * 36 + c4,                                            \
                 g_xt + (size_t)(m0 + row) * 1024 + (c) * 32 + c4);             \
        }                                                                       \
        _Pragma("unroll")                                                       \
        for (int q = 0; q < 2; q++) {                                           \
            int o = tid + q * 256;                                              \
            int row = o >> 4, c4 = (o & 15) << 2;                               \
            cp16(Bs + row * 68 + c4,                                            \
                 Wp + (size_t)((c) * 32 + row) * 1024 + col0 + c4);             \
        }                                                                       \
    }

    S1_ISSUE(0); CP_COMMIT();

    for (int c = 0; c < 32; c++) {
        CP_WAIT0();
        __syncthreads();
        if (c < 31) { S1_ISSUE(c + 1); CP_COMMIT(); }

        const float* As = s1 + (c & 1) * 6784;
        const float* Bs = As + 4608;
#pragma unroll
        for (int kk = 0; kk < 4; kk++) {
            wmma::fragment<wmma::matrix_a, 16, 16, 8, wmma::precision::tf32, wmma::row_major> a0, a1;
            wmma::load_matrix_sync(a0, As + (mrow * 32) * 36 + kk * 8, 36);
            wmma::load_matrix_sync(a1, As + (mrow * 32 + 16) * 36 + kk * 8, 36);
            wmma::fragment<wmma::matrix_b, 16, 16, 8, wmma::precision::tf32, wmma::row_major> b0, b1;
            wmma::load_matrix_sync(b0, Bs + (kk * 8) * 68 + ncol * 32, 68);
            wmma::load_matrix_sync(b1, Bs + (kk * 8) * 68 + ncol * 32 + 16, 68);
            wmma::mma_sync(acc[0][0], a0, b0, acc[0][0]);
            wmma::mma_sync(acc[0][1], a0, b1, acc[0][1]);
            wmma::mma_sync(acc[1][0], a1, b0, acc[1][0]);
            wmma::mma_sync(acc[1][1], a1, b1, acc[1][1]);
        }
        __syncthreads();
    }
#undef S1_ISSUE

#pragma unroll
    for (int mi = 0; mi < 2; mi++)
#pragma unroll
        for (int ni = 0; ni < 2; ni++)
            wmma::store_matrix_sync(
                g_gates + (size_t)gate * TBH
                        + (size_t)(m0 + mrow * 32 + mi * 16) * 1024
                        + col0 + ncol * 32 + ni * 16,
                acc[mi][ni], 1024, wmma::mem_row_major);
}

// ---------------------------------------------------------------------------
// Persistent recurrence: 64 CTAs x 256 thr, owner-computes (CTA c: cols
// [16c,16c+16) of all 3 gates). NO grid barrier: per-CTA publication flags,
// chunk-granular acquire polls. 8 warps = 4 kgrp(K=256) x 2 mpair(32 rows).
// Dyn smem 126976 B: hb[2][4][64][36] | Wb[2][4][32][52]; red=Wb, pre=hb.
// ---------------------------------------------------------------------------
#define REC_SMEM 126976

__global__ __launch_bounds__(NTHR, 1)
void recur_kernel(const float* __restrict__ b_ir, const float* __restrict__ b_hr,
                  const float* __restrict__ b_iz, const float* __restrict__ b_hz,
                  const float* __restrict__ b_in, const float* __restrict__ b_hn,
                  float* __restrict__ out, int write_hfinal) {
    extern __shared__ __align__(16) float sm[];
    float* hb  = sm;            // 2*4*64*36 = 18432 fl
    float* Wb  = sm + 18432;    // 2*4*32*52 = 13312 fl
    float* red = Wb;            // 3*64*48 fl (post-loop alias)
    float* pre = sm;            // 64*48 fl (post-loop alias)

    const int cta   = blockIdx.x;
    const int tid   = threadIdx.x;
    const int wid   = tid >> 5;
    const int kgrp  = wid >> 1;           // 0..3
    const int mpair = wid & 1;            // rows [32*mpair, +32)
    const int col0  = cta << 4;

    // monotonic flag base (settled: previous replay finished all steps)
    const unsigned base = *(volatile unsigned*)&g_flags[cta];

    // pointwise fixed (row,col) ownership
    const int c_pb = tid & 15;
    const int r_pb = tid >> 4;
    const int jcol = col0 + c_pb;
    const float vb_ir = b_ir[jcol], vb_hr = b_hr[jcol];
    const float vb_iz = b_iz[jcol], vb_hz = b_hz[jcol];
    const float vb_in = b_in[jcol], vb_hn = b_hn[jcol];

    float pg_r[4], pg_z[4], pg_n[4];
    float hpq[4] = {0.f, 0.f, 0.f, 0.f};

#pragma unroll
    for (int q = 0; q < 4; q++) {
        size_t gi = (size_t)(r_pb + q * 16) * 1024 + jcol;
        pg_r[q] = g_gates[gi];
        pg_z[q] = g_gates[TBH + gi];
        pg_n[q] = g_gates[2ull * TBH + gi];
    }

    for (int t = 0; t < TSZ; t++) {
        if (t > 0) {
            // ========= Phase A: hW [64 x 48] from h_{t-1} =========
            const float* hsrc = g_ht[(t - 1) & 1];
            const unsigned tgt = base + (unsigned)t;    // flag value after step t-1

            wmma::fragment<wmma::accumulator, 16, 16, 8, float> acc[2][3];
#pragma unroll
            for (int mi = 0; mi < 2; mi++)
#pragma unroll
                for (int g = 0; g < 3; g++) wmma::fill_fragment(acc[mi][g], 0.0f);

#define R_ISSUE(c)                                                              \
            {                                                                   \
                int kofs = (c) * 32;                                            \
                _Pragma("unroll")                                               \
                for (int q = 0; q < 8; q++) {                                   \
                    int o = tid + q * 256;                                      \
                    int kg = o >> 9, idx = o & 511;                             \
                    int row = idx >> 3, c4 = (idx & 7) << 2;                    \
                    cp16(hb + (((c) & 1) * 4 + kg) * 2304 + row * 36 + c4,      \
                         hsrc + (size_t)row * 1024 + kg * 256 + kofs + c4);     \
                }                                                               \
                _Pragma("unroll")                                               \
                for (int q = 0; q < 6; q++) {                                   \
                    int o = tid + q * 256;                                      \
                    int kg = o / 384, idx = o - kg * 384;                       \
                    int row = idx / 12, cw = (idx % 12) << 2;                   \
                    int gate = cw >> 4;                                         \
                    cp16(Wb + (((c) & 1) * 4 + kg) * 1664 + row * 52 + cw,      \
                         g_Wall + (size_t)gate * 1048576                        \
                                + (size_t)(kg * 256 + kofs + row) * 1024        \
                                + col0 + (cw & 15));                            \
                }                                                               \
            }

            poll_chunk(0, tgt, tid);
            __syncthreads();
            R_ISSUE(0); CP_COMMIT();

            for (int it = 0; it < 8; it++) {
                if (it < 7) poll_chunk(it + 1, tgt, tid);   // overlaps in-flight cp
                CP_WAIT0();
                __syncthreads();
                if (it < 7) { R_ISSUE(it + 1); CP_COMMIT(); }

                const float* A  = hb + ((it & 1) * 4 + kgrp) * 2304 + (mpair * 32) * 36;
                const float* Bp = Wb + ((it & 1) * 4 + kgrp) * 1664;
#pragma unroll
                for (int kk = 0; kk < 4; kk++) {
                    wmma::fragment<wmma::matrix_a, 16, 16, 8, wmma::precision::tf32, wmma::row_major> a0, a1;
                    wmma::load_matrix_sync(a0, A + kk * 8, 36);
                    wmma::load_matrix_sync(a1, A + 16 * 36 + kk * 8, 36);
#pragma unroll
                    for (int g = 0; g < 3; g++) {
                        wmma::fragment<wmma::matrix_b, 16, 16, 8, wmma::precision::tf32, wmma::row_major> bf;
                        wmma::load_matrix_sync(bf, Bp + (kk * 8) * 52 + g * 16, 52);
                        wmma::mma_sync(acc[0][g], a0, bf, acc[0][g]);
                        wmma::mma_sync(acc[1][g], a1, bf, acc[1][g]);
                    }
                }
                __syncthreads();
            }
#undef R_ISSUE

            // K-split reduction: kgrp 1..3 publish, kgrp 0 combines -> pre
            if (kgrp > 0) {
                float* s = red + (size_t)(kgrp - 1) * 3072;
#pragma unroll
                for (int mi = 0; mi < 2; mi++)
#pragma unroll
                    for (int g = 0; g < 3; g++)
                        wmma::store_matrix_sync(s + (mpair * 32 + mi * 16) * 48 + g * 16,
                                                acc[mi][g], 48, wmma::mem_row_major);
            }
            __syncthreads();
            if (kgrp == 0) {
#pragma unroll
                for (int src = 0; src < 3; src++) {
                    const float* s = red + (size_t)src * 3072;
#pragma unroll
                    for (int mi = 0; mi < 2; mi++)
#pragma unroll
                        for (int g = 0; g < 3; g++) {
                            wmma::fragment<wmma::accumulator, 16, 16, 8, float> p;
                            wmma::load_matrix_sync(p, s + (mpair * 32 + mi * 16) * 48 + g * 16,
                                                   48, wmma::mem_row_major);
#pragma unroll
                            for (int e = 0; e < p.num_elements; e++)
                                acc[mi][g].x[e] += p.x[e];
                        }
                }
#pragma unroll
                for (int mi = 0; mi < 2; mi++)
#pragma unroll
                    for (int g = 0; g < 3; g++)
                        wmma::store_matrix_sync(pre + (mpair * 32 + mi * 16) * 48 + g * 16,
                                                acc[mi][g], 48, wmma::mem_row_major);
            }
            __syncthreads();
        }

        // ========= Phase B: pointwise (gates & h_prev in regs) =========
        {
            const size_t toff = (size_t)t * BH;
            float* hw = out + toff;
#pragma unroll
            for (int q = 0; q < 4; q++) {
                int row = r_pb + q * 16;
                int gi  = row * 1024 + jcol;

                float gr = pg_r[q] + vb_ir;
                float gz = pg_z[q] + vb_iz;
                float gn = pg_n[q] + vb_in;
                float hr = vb_hr, hz = vb_hz, hn = vb_hn;
                if (t > 0) {
                    hr += pre[row * 48 + c_pb];
                    hz += pre[row * 48 + 16 + c_pb];
                    hn += pre[row * 48 + 32 + c_pb];
                }
                float r = 1.0f / (1.0f + expf(-(gr + hr)));
                float z = 1.0f / (1.0f + expf(-(gz + hz)));
                float n = tanhf(gn + r * hn);
                float hnew = (1.0f - z) * n + z * hpq[q];

                hpq[q] = hnew;
                hw[gi] = hnew;
                g_ht[t & 1][gi] = wmma::__float_to_tf32(hnew);
                if (t == TSZ - 1 && write_hfinal) out[TBH + gi] = hnew;
            }
        }

        // ========= Publish own h for step t (release after block-wide sync) ====
        __syncthreads();
        if (tid == 0) st_rel(&g_flags[cta], base + (unsigned)t + 1u);

        // prefetch gates for t+1 (overlaps consumers' ramp-up)
        if (t < TSZ - 1) {
            const size_t toff1 = (size_t)(t + 1) * BH;
#pragma unroll
            for (int q = 0; q < 4; q++) {
                size_t gi = toff1 + (size_t)(r_pb + q * 16) * 1024 + jcol;
                pg_r[q] = g_gates[gi];
                pg_z[q] = g_gates[TBH + gi];
                pg_n[q] = g_gates[2ull * TBH + gi];
            }
        }
    }
}

// ---------------------------------------------------------------------------
extern "C" void kernel_launch(void* const* d_in, const int* in_sizes, int n_in,
                              void* d_out, int out_size) {
    const float* x    = (const float*)d_in[0];
    const float* W_ir = (const float*)d_in[1];
    const float* b_ir = (const float*)d_in[2];
    const float* W_hr = (const float*)d_in[3];
    const float* b_hr = (const float*)d_in[4];
    const float* W_iz = (const float*)d_in[5];
    const float* b_iz = (const float*)d_in[6];
    const float* W_hz = (const float*)d_in[7];
    const float* b_hz = (const float*)d_in[8];
    const float* W_in = (const float*)d_in[9];
    const float* b_in = (const float*)d_in[10];
    const float* W_hn = (const float*)d_in[11];
    const float* b_hn = (const float*)d_in[12];
    float* out = (float*)d_out;

    const int has_hfinal = ((size_t)out_size >= TBH + (size_t)BH) ? 1 : 0;

    static int attr_done = 0;
    if (!attr_done) {
        cudaFuncSetAttribute(recur_kernel,
                             cudaFuncAttributeMaxDynamicSharedMemorySize, REC_SMEM);
        cudaFuncSetAttribute(stage1_kernel,
                             cudaFuncAttributeMaxDynamicSharedMemorySize, S1_SMEM);
        attr_done = 1;
    }

    wconv_kernel<<<1024, 256>>>(W_hr, 0);
    wconv_kernel<<<1024, 256>>>(W_hz, 1);
    wconv_kernel<<<1024, 256>>>(W_hn, 2);
    wconv_kernel<<<1024, 256>>>(W_ir, 3);
    wconv_kernel<<<1024, 256>>>(W_iz, 4);
    wconv_kernel<<<1024, 256>>>(W_in, 5);
    xprep_kernel<<<32768, 256>>>(x);

    stage1_kernel<<<dim3(48, 256), 256, S1_SMEM>>>();

    recur_kernel<<<NCTA, NTHR, REC_SMEM>>>(
        b_ir, b_hr, b_iz, b_hz, b_in, b_hn, out, has_hfinal);
}